// round 3
// baseline (speedup 1.0000x reference)
#include <cuda_runtime.h>

#define NA      8192
#define DD      128
#define HH      256
#define ROWS_A  8
#define TILE_J  512
#define ROWS_B  32
#define KC      16

// Scratch (static __device__ — no allocation)
// g_pos4: (x, y, z, s) in angstrom; s = |p|^2 computed with reference rounding
__device__ float4 g_pos4[NA];
__device__ float  g_feat[NA * 256];
__device__ float  g_partial[NA / ROWS_B];

// ---------------------------------------------------------------------------
// Prep: nm -> angstrom scaling; s = ((x*x)+(y*y))+(z*z) with NO fma
// contraction (matches XLA's mul+add elementwise/reduce fusion).
// ---------------------------------------------------------------------------
__global__ void k_prep(const float* __restrict__ pos) {
    int i = blockIdx.x * 256 + threadIdx.x;
    if (i < NA) {
        float x = __fmul_rn(10.0f, pos[3 * i + 0]);
        float y = __fmul_rn(10.0f, pos[3 * i + 1]);
        float z = __fmul_rn(10.0f, pos[3 * i + 2]);
        float s = __fadd_rn(__fadd_rn(__fmul_rn(x, x), __fmul_rn(y, y)),
                            __fmul_rn(z, z));
        g_pos4[i] = make_float4(x, y, z, s);
    }
}

// ---------------------------------------------------------------------------
// Fused radius-graph + sparse distance-weighted aggregation.
// d2 replicates the reference bit-for-bit:
//   dot = fma(z,z, fma(y,y, x*x))        (gemm k-chain)
//   d2  = RN(RN(s_i + s_j) - 2*dot)      (cancellation-prone form -> noisy
//                                         diagonal; ~half the self-edges are
//                                         IN the reference graph with phi~1)
// ---------------------------------------------------------------------------
__global__ void __launch_bounds__(128) k_agg(const float* __restrict__ emb,
                                             const int* __restrict__ types) {
    __shared__ float s_phi[TILE_J * ROWS_A];   // worst case: every pair hits
    __shared__ int   s_meta[TILE_J * ROWS_A];
    __shared__ int   s_cnt;

    const int t    = threadIdx.x;
    const int row0 = blockIdx.x * ROWS_A;

    float4 rp[ROWS_A];
    #pragma unroll
    for (int r = 0; r < ROWS_A; r++) rp[r] = g_pos4[row0 + r];

    float acc[ROWS_A];
    #pragma unroll
    for (int r = 0; r < ROWS_A; r++) acc[r] = 0.0f;

    for (int base = 0; base < NA; base += TILE_J) {
        if (t == 0) s_cnt = 0;
        __syncthreads();

        #pragma unroll
        for (int k = 0; k < TILE_J / 128; k++) {
            int    j  = base + k * 128 + t;
            float4 pj = g_pos4[j];
            #pragma unroll
            for (int r = 0; r < ROWS_A; r++) {
                float dot = __fmul_rn(rp[r].x, pj.x);          // fma(x,x,0)
                dot = fmaf(rp[r].y, pj.y, dot);
                dot = fmaf(rp[r].z, pj.z, dot);
                float t1 = __fadd_rn(rp[r].w, pj.w);           // s_i + s_j
                float d2 = __fadd_rn(t1, __fmul_rn(-2.0f, dot));
                if (d2 > 1e-12f) {
                    float d = __fsqrt_rn(d2);
                    if (d <= 5.0f) {
                        float phi = expf(-d);
                        int idx   = atomicAdd(&s_cnt, 1);
                        s_phi[idx]  = phi;
                        s_meta[idx] = __ldg(types + j) | (r << 16);
                    }
                }
            }
        }
        __syncthreads();

        int cnt = s_cnt;
        for (int e = 0; e < cnt; e++) {
            float phi  = s_phi[e];
            int   meta = s_meta[e];
            int   type = meta & 0xFFFF;
            int   r    = meta >> 16;
            float hv   = emb[type * DD + t];   // emb is 51KB -> L1 resident
            #pragma unroll
            for (int rr = 0; rr < ROWS_A; rr++)
                if (rr == r) acc[rr] = fmaf(phi, hv, acc[rr]);
        }
        __syncthreads();
    }

    #pragma unroll
    for (int r = 0; r < ROWS_A; r++) {
        int i    = row0 + r;
        int type = types[i];
        g_feat[i * 256 + t]       = emb[type * DD + t];   // h_i
        g_feat[i * 256 + 128 + t] = acc[r];                // agg_i
    }
}

// ---------------------------------------------------------------------------
// Per-node MLP: e_node = relu(feat @ W1) @ w2, partial sum per block.
// 256 threads (one per hidden unit), ROWS_B rows/block, feat tile in smem,
// W1 chunks in registers, fp32 accumulators.
// ---------------------------------------------------------------------------
__global__ void __launch_bounds__(256) k_mlp(const float* __restrict__ W1,
                                             const float* __restrict__ w2) {
    __shared__ float s_feat[ROWS_B * 256];
    __shared__ float s_red[256];

    const int u    = threadIdx.x;     // hidden unit
    const int row0 = blockIdx.x * ROWS_B;

    {   // cooperative load of ROWS_B feature rows (contiguous), vectorized
        const float4* src = (const float4*)(g_feat + row0 * 256);
        float4*       dst = (float4*)s_feat;
        #pragma unroll
        for (int k = 0; k < (ROWS_B * 64) / 256; k++)
            dst[k * 256 + u] = src[k * 256 + u];
    }
    __syncthreads();

    float acc[ROWS_B];
    #pragma unroll
    for (int r = 0; r < ROWS_B; r++) acc[r] = 0.0f;

    for (int kk = 0; kk < 2 * DD; kk += KC) {
        float w[KC];
        #pragma unroll
        for (int m = 0; m < KC; m++) w[m] = W1[(kk + m) * HH + u];

        #pragma unroll
        for (int m4 = 0; m4 < KC / 4; m4++) {
            #pragma unroll
            for (int r = 0; r < ROWS_B; r++) {
                float4 f = *(const float4*)(s_feat + r * 256 + kk + m4 * 4);
                acc[r] = fmaf(f.x, w[m4 * 4 + 0], acc[r]);
                acc[r] = fmaf(f.y, w[m4 * 4 + 1], acc[r]);
                acc[r] = fmaf(f.z, w[m4 * 4 + 2], acc[r]);
                acc[r] = fmaf(f.w, w[m4 * 4 + 3], acc[r]);
            }
        }
    }

    float p = 0.0f;
    #pragma unroll
    for (int r = 0; r < ROWS_B; r++) p += fmaxf(acc[r], 0.0f);
    p *= w2[u];

    s_red[u] = p;
    __syncthreads();
    for (int s = 128; s > 0; s >>= 1) {
        if (u < s) s_red[u] += s_red[u + s];
        __syncthreads();
    }
    if (u == 0) g_partial[blockIdx.x] = s_red[0];
}

// ---------------------------------------------------------------------------
// Final deterministic reduction + unit conversion (kJ/mol -> kcal/mol)
// ---------------------------------------------------------------------------
__global__ void k_reduce(float* __restrict__ out) {
    __shared__ float s[NA / ROWS_B];
    int t = threadIdx.x;
    s[t]  = g_partial[t];
    __syncthreads();
    for (int k = (NA / ROWS_B) / 2; k > 0; k >>= 1) {
        if (t < k) s[t] += s[t + k];
        __syncthreads();
    }
    if (t == 0) out[0] = s[0] * 0.2390057361376673f;
}

// ---------------------------------------------------------------------------
extern "C" void kernel_launch(void* const* d_in, const int* in_sizes, int n_in,
                              void* d_out, int out_size) {
    const float* pos   = (const float*)d_in[0];
    const int*   types = (const int*)d_in[1];
    const float* emb   = (const float*)d_in[2];
    const float* W1    = (const float*)d_in[3];
    const float* w2    = (const float*)d_in[4];
    float*       out   = (float*)d_out;

    k_prep  <<<(NA + 255) / 256, 256>>>(pos);
    k_agg   <<<NA / ROWS_A, 128>>>(emb, types);
    k_mlp   <<<NA / ROWS_B, 256>>>(W1, w2);
    k_reduce<<<1, NA / ROWS_B>>>(out);
}

// round 4
// speedup vs baseline: 2.3586x; 2.3586x over previous
#include <cuda_runtime.h>

#define NA      8192
#define DD      128
#define HH      256
#define ROWS_B  32
#define KC      16
#define NC1     12          // cells per dimension (box 60 A / cutoff 5 A)
#define NCELL   (NC1*NC1*NC1)
#define MAXN    192         // max neighbors per atom (mean ~21, Poisson tail ~0)

// Scratch (static __device__ — no allocation)
__device__ float4 g_pos4[NA];      // (x,y,z,s) angstrom; s = |p|^2 ref-rounded
__device__ int    g_cellid[NA];
__device__ int    g_count[NCELL];
__device__ int    g_cursor[NCELL];
__device__ int    g_start[NCELL];
__device__ int    g_slot[NA];      // cell-sorted original atom indices
__device__ float4 g_spos[NA];      // cell-sorted positions
__device__ int    g_stype[NA];     // cell-sorted types
__device__ float  g_feat[NA * 256];
__device__ float  g_partial[NA / ROWS_B];

// ---------------------------------------------------------------------------
__global__ void k_zero() {
    int c = blockIdx.x * 256 + threadIdx.x;
    if (c < NCELL) { g_count[c] = 0; g_cursor[c] = 0; }
}

// ---------------------------------------------------------------------------
// Prep: nm -> angstrom; s = ((x*x)+(y*y))+(z*z) with NO fma contraction
// (matches XLA's elementwise/reduce rounding). Also bin into 5A cells.
// ---------------------------------------------------------------------------
__global__ void k_prep(const float* __restrict__ pos) {
    int i = blockIdx.x * 256 + threadIdx.x;
    if (i < NA) {
        float x = __fmul_rn(10.0f, pos[3 * i + 0]);
        float y = __fmul_rn(10.0f, pos[3 * i + 1]);
        float z = __fmul_rn(10.0f, pos[3 * i + 2]);
        float s = __fadd_rn(__fadd_rn(__fmul_rn(x, x), __fmul_rn(y, y)),
                            __fmul_rn(z, z));
        g_pos4[i] = make_float4(x, y, z, s);
        int cx = min(NC1 - 1, max(0, (int)(x * 0.2f)));
        int cy = min(NC1 - 1, max(0, (int)(y * 0.2f)));
        int cz = min(NC1 - 1, max(0, (int)(z * 0.2f)));
        int c  = (cz * NC1 + cy) * NC1 + cx;
        g_cellid[i] = c;
        atomicAdd(&g_count[c], 1);
    }
}

// ---------------------------------------------------------------------------
// Exclusive prefix sum over 1728 cell counts (1 block, Hillis-Steele, 2048 pad)
// ---------------------------------------------------------------------------
__global__ void __launch_bounds__(1024) k_scan() {
    __shared__ int a[2048], b[2048];
    int t = threadIdx.x;
    #pragma unroll
    for (int k = 0; k < 2; k++) {
        int idx = t + 1024 * k;
        a[idx] = (idx < NCELL) ? g_count[idx] : 0;
    }
    __syncthreads();
    int* src = a; int* dst = b;
    for (int s = 1; s < 2048; s <<= 1) {
        #pragma unroll
        for (int k = 0; k < 2; k++) {
            int idx = t + 1024 * k;
            int v = src[idx];
            if (idx >= s) v += src[idx - s];
            dst[idx] = v;
        }
        __syncthreads();
        int* tmp = src; src = dst; dst = tmp;
    }
    #pragma unroll
    for (int k = 0; k < 2; k++) {
        int idx = t + 1024 * k;
        if (idx < NCELL) g_start[idx] = src[idx] - g_count[idx];
    }
}

// ---------------------------------------------------------------------------
__global__ void k_scatter() {
    int i = blockIdx.x * 256 + threadIdx.x;
    if (i < NA) {
        int c    = g_cellid[i];
        int slot = g_start[c] + atomicAdd(&g_cursor[c], 1);
        g_slot[slot] = i;
    }
}

// ---------------------------------------------------------------------------
// Per-cell: insertion-sort atom indices (deterministic order), then gather
// cell-sorted pos/type arrays.
// ---------------------------------------------------------------------------
__global__ void k_sortgather(const int* __restrict__ types) {
    int c = blockIdx.x * 256 + threadIdx.x;
    if (c < NCELL) {
        int st = g_start[c], cn = g_count[c];
        for (int i = 1; i < cn; i++) {
            int v = g_slot[st + i];
            int j = i - 1;
            while (j >= 0 && g_slot[st + j] > v) {
                g_slot[st + j + 1] = g_slot[st + j];
                j--;
            }
            g_slot[st + j + 1] = v;
        }
        for (int i = 0; i < cn; i++) {
            int a = g_slot[st + i];
            g_spos[st + i]  = g_pos4[a];
            g_stype[st + i] = types[a];
        }
    }
}

// ---------------------------------------------------------------------------
// Cell-list radius graph + sparse aggregation. 2 atoms / 256-thread block;
// per atom: 128 feature threads. 27 owner threads scan neighbor cells,
// building a deterministic hit list (cell-major, atom-ascending) via
// count pass + exclusive offset + write pass. Per-pair arithmetic is
// bit-identical to the reference:
//   dot = fma(z,z, fma(y,y, x*x));  d2 = RN(RN(s_i+s_j) - 2*dot)
// (noisy diagonal -> self-edges exactly as the dense reference produces)
// ---------------------------------------------------------------------------
__global__ void __launch_bounds__(256) k_agg(const float* __restrict__ emb) {
    __shared__ float s_phi [2][MAXN];
    __shared__ int   s_type[2][MAXN];
    __shared__ int   s_ccnt[2][27];
    __shared__ int   s_tot [2];

    const int t  = threadIdx.x;
    const int g  = t >> 7;          // atom group within block
    const int tl = t & 127;
    const int b  = blockIdx.x * 2 + g;   // sorted slot

    const float4 pi = g_spos[b];
    const int cx = min(NC1 - 1, max(0, (int)(pi.x * 0.2f)));
    const int cy = min(NC1 - 1, max(0, (int)(pi.y * 0.2f)));
    const int cz = min(NC1 - 1, max(0, (int)(pi.z * 0.2f)));

    // --- pass A: count hits per neighbor cell ---
    int nx = 0, ny = 0, nz = 0, valid = 0;
    if (tl < 27) {
        nx = cx + tl % 3 - 1;
        ny = cy + (tl / 3) % 3 - 1;
        nz = cz + tl / 9 - 1;
        valid = (nx >= 0) & (nx < NC1) & (ny >= 0) & (ny < NC1)
              & (nz >= 0) & (nz < NC1);
        int n = 0;
        if (valid) {
            int c  = (nz * NC1 + ny) * NC1 + nx;
            int st = g_start[c], en = st + g_count[c];
            for (int k = st; k < en; k++) {
                float4 pj = g_spos[k];
                float dot = __fmul_rn(pi.x, pj.x);
                dot = fmaf(pi.y, pj.y, dot);
                dot = fmaf(pi.z, pj.z, dot);
                float t1 = __fadd_rn(pi.w, pj.w);
                float d2 = __fadd_rn(t1, __fmul_rn(-2.0f, dot));
                if (d2 > 1e-12f) {
                    float d = __fsqrt_rn(d2);
                    if (d <= 5.0f) n++;
                }
            }
        }
        s_ccnt[g][tl] = n;
    }
    __syncthreads();

    // --- pass B: exclusive offset, recompute + write hits ---
    if (tl < 27) {
        int off = 0;
        #pragma unroll 1
        for (int q = 0; q < tl; q++) off += s_ccnt[g][q];
        if (tl == 26) s_tot[g] = off + s_ccnt[g][26];
        if (valid) {
            int c  = (nz * NC1 + ny) * NC1 + nx;
            int st = g_start[c], en = st + g_count[c];
            for (int k = st; k < en; k++) {
                float4 pj = g_spos[k];
                float dot = __fmul_rn(pi.x, pj.x);
                dot = fmaf(pi.y, pj.y, dot);
                dot = fmaf(pi.z, pj.z, dot);
                float t1 = __fadd_rn(pi.w, pj.w);
                float d2 = __fadd_rn(t1, __fmul_rn(-2.0f, dot));
                if (d2 > 1e-12f) {
                    float d = __fsqrt_rn(d2);
                    if (d <= 5.0f && off < MAXN) {
                        s_phi [g][off] = expf(-d);
                        s_type[g][off] = g_stype[k];
                        off++;
                    }
                }
            }
        }
    }
    __syncthreads();

    // --- phase 2: 128 feature threads drain the hit list ---
    float acc = 0.0f;
    const int tot = s_tot[g];
    #pragma unroll 4
    for (int e = 0; e < tot; e++)
        acc = fmaf(s_phi[g][e], emb[s_type[g][e] * DD + tl], acc);

    const int i = g_slot[b];                 // original atom index
    g_feat[i * 256 + tl]       = emb[g_stype[b] * DD + tl];  // h_i
    g_feat[i * 256 + 128 + tl] = acc;                         // agg_i
}

// ---------------------------------------------------------------------------
// Per-node MLP: e_node = relu(feat @ W1) @ w2, partial sum per block.
// ---------------------------------------------------------------------------
__global__ void __launch_bounds__(256) k_mlp(const float* __restrict__ W1,
                                             const float* __restrict__ w2) {
    __shared__ float s_feat[ROWS_B * 256];
    __shared__ float s_red[256];

    const int u    = threadIdx.x;
    const int row0 = blockIdx.x * ROWS_B;

    {
        const float4* src = (const float4*)(g_feat + row0 * 256);
        float4*       dst = (float4*)s_feat;
        #pragma unroll
        for (int k = 0; k < (ROWS_B * 64) / 256; k++)
            dst[k * 256 + u] = src[k * 256 + u];
    }
    __syncthreads();

    float acc[ROWS_B];
    #pragma unroll
    for (int r = 0; r < ROWS_B; r++) acc[r] = 0.0f;

    for (int kk = 0; kk < 2 * DD; kk += KC) {
        float w[KC];
        #pragma unroll
        for (int m = 0; m < KC; m++) w[m] = W1[(kk + m) * HH + u];

        #pragma unroll
        for (int m4 = 0; m4 < KC / 4; m4++) {
            #pragma unroll
            for (int r = 0; r < ROWS_B; r++) {
                float4 f = *(const float4*)(s_feat + r * 256 + kk + m4 * 4);
                acc[r] = fmaf(f.x, w[m4 * 4 + 0], acc[r]);
                acc[r] = fmaf(f.y, w[m4 * 4 + 1], acc[r]);
                acc[r] = fmaf(f.z, w[m4 * 4 + 2], acc[r]);
                acc[r] = fmaf(f.w, w[m4 * 4 + 3], acc[r]);
            }
        }
    }

    float p = 0.0f;
    #pragma unroll
    for (int r = 0; r < ROWS_B; r++) p += fmaxf(acc[r], 0.0f);
    p *= w2[u];

    s_red[u] = p;
    __syncthreads();
    for (int s = 128; s > 0; s >>= 1) {
        if (u < s) s_red[u] += s_red[u + s];
        __syncthreads();
    }
    if (u == 0) g_partial[blockIdx.x] = s_red[0];
}

// ---------------------------------------------------------------------------
__global__ void k_reduce(float* __restrict__ out) {
    __shared__ float s[NA / ROWS_B];
    int t = threadIdx.x;
    s[t]  = g_partial[t];
    __syncthreads();
    for (int k = (NA / ROWS_B) / 2; k > 0; k >>= 1) {
        if (t < k) s[t] += s[t + k];
        __syncthreads();
    }
    if (t == 0) out[0] = s[0] * 0.2390057361376673f;
}

// ---------------------------------------------------------------------------
extern "C" void kernel_launch(void* const* d_in, const int* in_sizes, int n_in,
                              void* d_out, int out_size) {
    const float* pos   = (const float*)d_in[0];
    const int*   types = (const int*)d_in[1];
    const float* emb   = (const float*)d_in[2];
    const float* W1    = (const float*)d_in[3];
    const float* w2    = (const float*)d_in[4];
    float*       out   = (float*)d_out;

    k_zero      <<<(NCELL + 255) / 256, 256>>>();
    k_prep      <<<NA / 256, 256>>>(pos);
    k_scan      <<<1, 1024>>>();
    k_scatter   <<<NA / 256, 256>>>();
    k_sortgather<<<(NCELL + 255) / 256, 256>>>(types);
    k_agg       <<<NA / 2, 256>>>(emb);
    k_mlp       <<<NA / ROWS_B, 256>>>(W1, w2);
    k_reduce    <<<1, NA / ROWS_B>>>(out);
}